// round 1
// baseline (speedup 1.0000x reference)
#include <cuda_runtime.h>

#define N_NODES  8000
#define N_EDGES  32000
#define N_GRAPHS 32

// ---------------- scratch (device globals; no allocations anywhere) --------
__device__ float g_h1[N_NODES * 8];
__device__ float g_h2[N_NODES * 64];
__device__ float g_h3[N_NODES * 128];
__device__ float g_agg[N_NODES * 128];
__device__ float g_pool[N_GRAPHS * 128];

__device__ __forceinline__ float leaky(float v) { return v > 0.f ? v : 0.1f * v; }

// ---------------- utility: zero a buffer -----------------------------------
__global__ void zero_kernel(float* __restrict__ p, int n) {
    int i = blockIdx.x * blockDim.x + threadIdx.x;
    if (i < n) p[i] = 0.f;
}

// ---------------- fused NNConv edge kernel ----------------------------------
// Per block: TILE_E edges.
//   1. attr[e]   = (x[dst]-x[src])[1:4]
//   2. e_s[e,:]  = leaky(attr @ w1 + b1)           [TILE_E,64]
//   3. for i in 0..IN-1:
//        stage  w2[:, i*OUT:(i+1)*OUT] into SMEM   [64,OUT]
//        C      = e_s @ w2_slice + b2_slice        [TILE_E,OUT]  (register tiled)
//        acc   += h[src][i] * leaky(C)
//   4. atomicAdd acc into agg[dst]
template <int IN, int OUT, int TILE_E>
__global__ __launch_bounds__(256)
void edge_conv_kernel(const float* __restrict__ x,
                      const float* __restrict__ h,
                      const int*   __restrict__ ei,
                      const float* __restrict__ w1,
                      const float* __restrict__ b1,
                      const float* __restrict__ w2,
                      const float* __restrict__ b2,
                      float*       __restrict__ agg)
{
    constexpr int CT  = OUT / 4;      // column-group threads (each owns 4 cols)
    constexpr int ET  = 256 / CT;     // edge-group threads
    constexpr int EPT = TILE_E / ET;  // edges per thread

    extern __shared__ float smem[];
    float* e_s    = smem;                        // TILE_E * 68  (padded stride)
    float* h_s    = e_s + TILE_E * 68;           // TILE_E * IN
    float* w2_s   = h_s + TILE_E * IN;           // 64 * OUT
    float* b2_s   = w2_s + 64 * OUT;             // OUT
    float* attr_s = b2_s + OUT;                  // TILE_E * 3
    int*   src_s  = (int*)(attr_s + TILE_E * 3); // TILE_E
    int*   dst_s  = src_s + TILE_E;              // TILE_E

    const int tid = threadIdx.x;
    const int e0  = blockIdx.x * TILE_E;

    // --- edge indices + relative-position attributes
    for (int j = tid; j < TILE_E; j += 256) {
        int s = ei[e0 + j];
        int d = ei[N_EDGES + e0 + j];
        src_s[j] = s;
        dst_s[j] = d;
        attr_s[j * 3 + 0] = x[d * 4 + 1] - x[s * 4 + 1];
        attr_s[j * 3 + 1] = x[d * 4 + 2] - x[s * 4 + 2];
        attr_s[j * 3 + 2] = x[d * 4 + 3] - x[s * 4 + 3];
    }
    __syncthreads();

    // --- gather h[src] rows (vectorized; IN is a multiple of 4)
    for (int idx = tid; idx < TILE_E * (IN / 4); idx += 256) {
        int j = idx / (IN / 4), q = idx % (IN / 4);
        ((float4*)&h_s[j * IN])[q] = ((const float4*)&h[src_s[j] * IN])[q];
    }
    // --- edge hidden: e = leaky(attr @ w1 + b1)   (w1: [3,64] row-major)
    for (int idx = tid; idx < TILE_E * 64; idx += 256) {
        int j = idx >> 6, k = idx & 63;
        float a0 = attr_s[j * 3], a1 = attr_s[j * 3 + 1], a2 = attr_s[j * 3 + 2];
        e_s[j * 68 + k] = leaky(b1[k] + a0 * w1[k] + a1 * w1[64 + k] + a2 * w1[128 + k]);
    }

    const int ce = tid % CT;
    const int te = tid / CT;
    const int c0 = ce * 4;

    float acc[EPT][4];
#pragma unroll
    for (int j = 0; j < EPT; j++) { acc[j][0] = acc[j][1] = acc[j][2] = acc[j][3] = 0.f; }

    for (int i = 0; i < IN; i++) {
        __syncthreads();
        // stage w2 slice for input channel i: w2[k][i*OUT + o]
        for (int idx = tid * 4; idx < 64 * OUT; idx += 1024) {
            int k = idx / OUT, o = idx % OUT;
            *(float4*)&w2_s[idx] = *(const float4*)&w2[k * (IN * OUT) + i * OUT + o];
        }
        if (tid < OUT) b2_s[tid] = b2[i * OUT + tid];
        __syncthreads();

        float c[EPT][4];
#pragma unroll
        for (int j = 0; j < EPT; j++) {
            c[j][0] = b2_s[c0]; c[j][1] = b2_s[c0 + 1];
            c[j][2] = b2_s[c0 + 2]; c[j][3] = b2_s[c0 + 3];
        }

        for (int k = 0; k < 64; k += 4) {
            float4 w0 = *(const float4*)&w2_s[(k + 0) * OUT + c0];
            float4 wA = *(const float4*)&w2_s[(k + 1) * OUT + c0];
            float4 wB = *(const float4*)&w2_s[(k + 2) * OUT + c0];
            float4 wC = *(const float4*)&w2_s[(k + 3) * OUT + c0];
#pragma unroll
            for (int j = 0; j < EPT; j++) {
                int eg = te + j * ET;
                float4 ev = *(const float4*)&e_s[eg * 68 + k];
                c[j][0] += ev.x * w0.x + ev.y * wA.x + ev.z * wB.x + ev.w * wC.x;
                c[j][1] += ev.x * w0.y + ev.y * wA.y + ev.z * wB.y + ev.w * wC.y;
                c[j][2] += ev.x * w0.z + ev.y * wA.z + ev.z * wB.z + ev.w * wC.z;
                c[j][3] += ev.x * w0.w + ev.y * wA.w + ev.z * wB.w + ev.w * wC.w;
            }
        }

#pragma unroll
        for (int j = 0; j < EPT; j++) {
            int eg = te + j * ET;
            float hv = h_s[eg * IN + i];
            acc[j][0] += hv * leaky(c[j][0]);
            acc[j][1] += hv * leaky(c[j][1]);
            acc[j][2] += hv * leaky(c[j][2]);
            acc[j][3] += hv * leaky(c[j][3]);
        }
    }

#pragma unroll
    for (int j = 0; j < EPT; j++) {
        int eg = te + j * ET;
        int d  = dst_s[eg];
        atomicAdd(&agg[d * OUT + c0 + 0], acc[j][0]);
        atomicAdd(&agg[d * OUT + c0 + 1], acc[j][1]);
        atomicAdd(&agg[d * OUT + c0 + 2], acc[j][2]);
        atomicAdd(&agg[d * OUT + c0 + 3], acc[j][3]);
    }
}

// ---------------- node update: h_next = leaky(agg + h @ root + cb) ---------
__global__ void node_update_kernel(const float* __restrict__ h,
                                   const float* __restrict__ agg,
                                   const float* __restrict__ root,
                                   const float* __restrict__ cb,
                                   float* __restrict__ out,
                                   int IN, int OUT)
{
    int gid = blockIdx.x * blockDim.x + threadIdx.x;
    if (gid >= N_NODES * OUT) return;
    int n = gid / OUT, o = gid % OUT;
    float t = agg[gid] + cb[o];
    for (int i = 0; i < IN; i++) t += h[n * IN + i] * root[i * OUT + o];
    out[gid] = leaky(t);
}

// ---------------- sum-pool over sorted batch_index --------------------------
#define POOL_CHUNK 50
__global__ void pool_kernel(const float* __restrict__ h3,
                            const int*   __restrict__ batch,
                            float*       __restrict__ g)
{
    int o  = threadIdx.x;                  // 128
    int n0 = blockIdx.x * POOL_CHUNK;
    int n1 = n0 + POOL_CHUNK; if (n1 > N_NODES) n1 = N_NODES;
    float s = 0.f;
    int cur = batch[n0];
    for (int n = n0; n < n1; n++) {
        int b = batch[n];
        if (b != cur) { atomicAdd(&g[cur * 128 + o], s); s = 0.f; cur = b; }
        s += h3[n * 128 + o];
    }
    atomicAdd(&g[cur * 128 + o], s);
}

// ---------------- readout MLP: 128->128->64->1 ------------------------------
__global__ void readout_kernel(const float* __restrict__ g,
                               const float* __restrict__ w1, const float* __restrict__ b1,
                               const float* __restrict__ w2, const float* __restrict__ b2,
                               const float* __restrict__ w3, const float* __restrict__ b3,
                               float* __restrict__ out)
{
    __shared__ float gin[128], g1[128], g2[64];
    int b = blockIdx.x, t = threadIdx.x;   // 128 threads
    gin[t] = g[b * 128 + t];
    __syncthreads();
    float s = b1[t];
    for (int i = 0; i < 128; i++) s += gin[i] * w1[i * 128 + t];
    g1[t] = leaky(s);
    __syncthreads();
    if (t < 64) {
        float s2 = b2[t];
        for (int i = 0; i < 128; i++) s2 += g1[i] * w2[i * 64 + t];
        g2[t] = leaky(s2);
    }
    __syncthreads();
    if (t < 64) g1[t] = g2[t] * w3[t];
    __syncthreads();
    if (t == 0) {
        float s3 = b3[0];
        for (int i = 0; i < 64; i++) s3 += g1[i];
        out[b] = s3;
    }
}

// ---------------- launch ----------------------------------------------------
static constexpr int smem_bytes(int IN, int OUT, int TE) {
    return 4 * (TE * 68 + TE * IN + 64 * OUT + OUT + TE * 3) + 8 * TE;
}

extern "C" void kernel_launch(void* const* d_in, const int* in_sizes, int n_in,
                              void* d_out, int out_size)
{
    const float* x       = (const float*)d_in[0];
    const int*   ei      = (const int*)  d_in[1];
    const int*   batch   = (const int*)  d_in[2];
    const float* en1_w1  = (const float*)d_in[3];
    const float* en1_b1  = (const float*)d_in[4];
    const float* en1_w2  = (const float*)d_in[5];
    const float* en1_b2  = (const float*)d_in[6];
    const float* en2_w1  = (const float*)d_in[7];
    const float* en2_b1  = (const float*)d_in[8];
    const float* en2_w2  = (const float*)d_in[9];
    const float* en2_b2  = (const float*)d_in[10];
    const float* en3_w1  = (const float*)d_in[11];
    const float* en3_b1  = (const float*)d_in[12];
    const float* en3_w2  = (const float*)d_in[13];
    const float* en3_b2  = (const float*)d_in[14];
    const float* root1   = (const float*)d_in[15];
    const float* cb1     = (const float*)d_in[16];
    const float* root2   = (const float*)d_in[17];
    const float* cb2     = (const float*)d_in[18];
    const float* root3   = (const float*)d_in[19];
    const float* cb3     = (const float*)d_in[20];
    const float* fc1_w   = (const float*)d_in[21];
    const float* fc1_b   = (const float*)d_in[22];
    const float* fc2_w   = (const float*)d_in[23];
    const float* fc2_b   = (const float*)d_in[24];
    const float* fc3_w   = (const float*)d_in[25];
    const float* fc3_b   = (const float*)d_in[26];

    float *h1, *h2, *h3, *agg, *gp;
    cudaGetSymbolAddress((void**)&h1,  g_h1);
    cudaGetSymbolAddress((void**)&h2,  g_h2);
    cudaGetSymbolAddress((void**)&h3,  g_h3);
    cudaGetSymbolAddress((void**)&agg, g_agg);
    cudaGetSymbolAddress((void**)&gp,  g_pool);

    constexpr int S1 = smem_bytes(4, 8, 128);
    constexpr int S2 = smem_bytes(8, 64, 64);
    constexpr int S3 = smem_bytes(64, 128, 64);
    cudaFuncSetAttribute(edge_conv_kernel<64, 128, 64>,
                         cudaFuncAttributeMaxDynamicSharedMemorySize, S3);

    // ---- layer 1: in=4, out=8
    zero_kernel<<<(N_NODES * 8 + 255) / 256, 256>>>(agg, N_NODES * 8);
    edge_conv_kernel<4, 8, 128><<<N_EDGES / 128, 256, S1>>>(
        x, x, ei, en1_w1, en1_b1, en1_w2, en1_b2, agg);
    node_update_kernel<<<(N_NODES * 8 + 255) / 256, 256>>>(x, agg, root1, cb1, h1, 4, 8);

    // ---- layer 2: in=8, out=64
    zero_kernel<<<(N_NODES * 64 + 255) / 256, 256>>>(agg, N_NODES * 64);
    edge_conv_kernel<8, 64, 64><<<N_EDGES / 64, 256, S2>>>(
        x, h1, ei, en2_w1, en2_b1, en2_w2, en2_b2, agg);
    node_update_kernel<<<(N_NODES * 64 + 255) / 256, 256>>>(h1, agg, root2, cb2, h2, 8, 64);

    // ---- layer 3: in=64, out=128
    zero_kernel<<<(N_NODES * 128 + 255) / 256, 256>>>(agg, N_NODES * 128);
    edge_conv_kernel<64, 128, 64><<<N_EDGES / 64, 256, S3>>>(
        x, h2, ei, en3_w1, en3_b1, en3_w2, en3_b2, agg);
    node_update_kernel<<<(N_NODES * 128 + 255) / 256, 256>>>(h2, agg, root3, cb3, h3, 64, 128);

    // ---- pool + readout
    zero_kernel<<<(N_GRAPHS * 128 + 255) / 256, 256>>>(gp, N_GRAPHS * 128);
    pool_kernel<<<(N_NODES + POOL_CHUNK - 1) / POOL_CHUNK, 128>>>(h3, batch, gp);
    readout_kernel<<<N_GRAPHS, 128>>>(gp, fc1_w, fc1_b, fc2_w, fc2_b, fc3_w, fc3_b,
                                      (float*)d_out);
}

// round 5
// speedup vs baseline: 2.3592x; 2.3592x over previous
#include <cuda_runtime.h>
#include <cuda_bf16.h>
#include <cstdint>

#define N_NODES  8000
#define N_EDGES  32000
#define N_GRAPHS 32

// ---------------- scratch (device globals; no allocations anywhere) --------
__device__ float g_h1[N_NODES * 8];
__device__ float g_h2[N_NODES * 64];
__device__ float g_h3[N_NODES * 128];
__device__ float g_agg[N_NODES * 128];
__device__ float g_pool[N_GRAPHS * 128];
// layer-3 w2 rearranged into mma.sync B-fragment order, bf16 hi/lo split.
// index = ((og*64 + i)*4 + kt)*32 + lane ; each entry = {b32(b0,b1), b32(b2,b3)}
__device__ uint2 g_bfrag_hi[16 * 64 * 4 * 32];
__device__ uint2 g_bfrag_lo[16 * 64 * 4 * 32];

__device__ __forceinline__ float leaky(float v) { return v > 0.f ? v : 0.1f * v; }

__device__ __forceinline__ uint32_t pack_bf2(float x, float y) {
    __nv_bfloat16 bx = __float2bfloat16(x);
    __nv_bfloat16 by = __float2bfloat16(y);
    uint16_t ux = *(uint16_t*)&bx, uy = *(uint16_t*)&by;
    return (uint32_t)ux | ((uint32_t)uy << 16);
}

// mma.sync m16n8k16 row.col f32 += bf16*bf16 (accumulate in place)
__device__ __forceinline__ void mma_acc(float* d, const uint32_t* a,
                                        uint32_t b0, uint32_t b1) {
    asm volatile(
        "mma.sync.aligned.m16n8k16.row.col.f32.bf16.bf16.f32 "
        "{%0,%1,%2,%3}, {%4,%5,%6,%7}, {%8,%9}, {%0,%1,%2,%3};"
        : "+f"(d[0]), "+f"(d[1]), "+f"(d[2]), "+f"(d[3])
        : "r"(a[0]), "r"(a[1]), "r"(a[2]), "r"(a[3]), "r"(b0), "r"(b1));
}

// ---------------- utility: zero a buffer -----------------------------------
__global__ void zero_kernel(float* __restrict__ p, int n) {
    int i = blockIdx.x * blockDim.x + threadIdx.x;
    if (i < n) p[i] = 0.f;
}

// ---------------- prep: w2 [64,8192] -> bf16 hi/lo B fragments --------------
// For mma.sync.m16n8k16 .col B: lane = g*4 + t4 (g = lane>>2, t4 = lane&3)
//   b0,b1 -> k = t4*2, t4*2+1 ; col = g
//   b2,b3 -> k = t4*2+8, +9  ; col = g
// global col = i*128 + og*8 + g ; global k = kt*16 + local k
__global__ void prep_w2_frag(const float* __restrict__ w2,
                             uint2* __restrict__ fhi,
                             uint2* __restrict__ flo)
{
    int idx = blockIdx.x * blockDim.x + threadIdx.x;
    if (idx >= 16 * 64 * 4 * 32) return;
    int lane = idx & 31;
    int kt   = (idx >> 5) & 3;
    int i    = (idx >> 7) & 63;
    int og   = idx >> 13;
    int t4 = lane & 3, g = lane >> 2;
    int col = i * 128 + og * 8 + g;
    int k0  = kt * 16 + t4 * 2;

    float w00 = w2[(k0    ) * 8192 + col];
    float w01 = w2[(k0 + 1) * 8192 + col];
    float w10 = w2[(k0 + 8) * 8192 + col];
    float w11 = w2[(k0 + 9) * 8192 + col];

    __nv_bfloat16 h00 = __float2bfloat16(w00);
    __nv_bfloat16 h01 = __float2bfloat16(w01);
    __nv_bfloat16 h10 = __float2bfloat16(w10);
    __nv_bfloat16 h11 = __float2bfloat16(w11);
    float l00 = w00 - __bfloat162float(h00);
    float l01 = w01 - __bfloat162float(h01);
    float l10 = w10 - __bfloat162float(h10);
    float l11 = w11 - __bfloat162float(h11);

    uint16_t u00 = *(uint16_t*)&h00, u01 = *(uint16_t*)&h01;
    uint16_t u10 = *(uint16_t*)&h10, u11 = *(uint16_t*)&h11;
    fhi[idx] = make_uint2((uint32_t)u00 | ((uint32_t)u01 << 16),
                          (uint32_t)u10 | ((uint32_t)u11 << 16));
    flo[idx] = make_uint2(pack_bf2(l00, l01), pack_bf2(l10, l11));
}

// ---------------- layer-3 fused NNConv via mma.sync bf16 (compensated) ------
// Block = 128 edges, 256 threads = 8 warps, 16 edges/warp (one M16 row tile).
// A = edge-hidden e[16,64] per warp -> register fragments (hi/lo), built once.
// Loop og (16 groups of 8 output cols) x i (64 input channels):
//   D = sum_kt [ Ahi*Bhi + Ahi*Blo + Alo*Bhi ]  (two independent chains)
//   acc += h[src][i] * leaky(D + b2[col])
// After i loop: 4 atomicAdds per thread into agg[dst].
// SMEM word layout
#define W_EHI   0
#define W_ELO   4224
#define W_H     8448
#define W_B2    16640
#define W_ATTR  24832
#define W_SRC   25216
#define W_DST   25344
#define SMEM3_WORDS 25472
#define SMEM3_BYTES (SMEM3_WORDS * 4)

__global__ __launch_bounds__(256)
void edge_conv3_mma(const float* __restrict__ x,
                    const float* __restrict__ h,      // h2 [N,64]
                    const int*   __restrict__ ei,
                    const float* __restrict__ w1,
                    const float* __restrict__ b1,
                    const uint2* __restrict__ bfragHi,
                    const uint2* __restrict__ bfragLo,
                    const float* __restrict__ b2,
                    float*       __restrict__ agg)
{
    extern __shared__ uint32_t sm[];
    uint32_t* e_hi   = sm + W_EHI;     // [128 rows][33 words] packed bf16x2
    uint32_t* e_lo   = sm + W_ELO;
    float*    h_s    = (float*)(sm + W_H);     // [64][128] transposed
    float*    b2_s   = (float*)(sm + W_B2);    // [8192]
    float*    attr_s = (float*)(sm + W_ATTR);  // [128][3]
    int*      src_s  = (int*)(sm + W_SRC);
    int*      dst_s  = (int*)(sm + W_DST);

    const int tid = threadIdx.x;
    const int e0  = blockIdx.x * 128;

    // --- edge indices + relative-position attrs
    for (int j = tid; j < 128; j += 256) {
        int s = ei[e0 + j];
        int d = ei[N_EDGES + e0 + j];
        src_s[j] = s; dst_s[j] = d;
        attr_s[j * 3 + 0] = x[d * 4 + 1] - x[s * 4 + 1];
        attr_s[j * 3 + 1] = x[d * 4 + 2] - x[s * 4 + 2];
        attr_s[j * 3 + 2] = x[d * 4 + 3] - x[s * 4 + 3];
    }
    // --- bias slice to smem (2048 float4)
    for (int idx = tid; idx < 2048; idx += 256)
        ((float4*)b2_s)[idx] = ((const float4*)b2)[idx];
    __syncthreads();

    // --- edge hidden e = leaky(attr @ w1 + b1), split hi/lo, packed bf16x2
    for (int idx = tid; idx < 4096; idx += 256) {
        int row = idx >> 5, cp = idx & 31;
        float a0 = attr_s[row * 3], a1 = attr_s[row * 3 + 1], a2 = attr_s[row * 3 + 2];
        int c0 = cp * 2, c1 = c0 + 1;
        float v0 = leaky(b1[c0] + a0 * w1[c0] + a1 * w1[64 + c0] + a2 * w1[128 + c0]);
        float v1 = leaky(b1[c1] + a0 * w1[c1] + a1 * w1[64 + c1] + a2 * w1[128 + c1]);
        __nv_bfloat16 h0 = __float2bfloat16(v0);
        __nv_bfloat16 h1 = __float2bfloat16(v1);
        float l0 = v0 - __bfloat162float(h0);
        float l1 = v1 - __bfloat162float(h1);
        uint16_t u0 = *(uint16_t*)&h0, u1 = *(uint16_t*)&h1;
        e_hi[row * 33 + cp] = (uint32_t)u0 | ((uint32_t)u1 << 16);
        e_lo[row * 33 + cp] = pack_bf2(l0, l1);
    }
    // --- h[src] gathered transposed: h_s[i*128 + j]
    for (int idx = tid; idx < 128 * 16; idx += 256) {
        int j = idx & 127, q = idx >> 7;
        float4 v = ((const float4*)(h + src_s[j] * 64))[q];
        h_s[(4 * q + 0) * 128 + j] = v.x;
        h_s[(4 * q + 1) * 128 + j] = v.y;
        h_s[(4 * q + 2) * 128 + j] = v.z;
        h_s[(4 * q + 3) * 128 + j] = v.w;
    }
    __syncthreads();

    const int lane = tid & 31, w = tid >> 5;
    const int g = lane >> 2, t4 = lane & 3;
    const int row0 = w * 16 + g, row1 = row0 + 8;

    // --- A fragments in registers (built once, reused for all 1024 tiles)
    uint32_t aHi[4][4], aLo[4][4];
#pragma unroll
    for (int kt = 0; kt < 4; kt++) {
        int cp = kt * 8 + t4;
        aHi[kt][0] = e_hi[row0 * 33 + cp];
        aHi[kt][1] = e_hi[row1 * 33 + cp];
        aHi[kt][2] = e_hi[row0 * 33 + cp + 4];
        aHi[kt][3] = e_hi[row1 * 33 + cp + 4];
        aLo[kt][0] = e_lo[row0 * 33 + cp];
        aLo[kt][1] = e_lo[row1 * 33 + cp];
        aLo[kt][2] = e_lo[row0 * 33 + cp + 4];
        aLo[kt][3] = e_lo[row1 * 33 + cp + 4];
    }

    const int d0 = dst_s[row0], d1 = dst_s[row1];

    for (int og = 0; og < 16; og++) {
        float acc0 = 0.f, acc1 = 0.f, acc2 = 0.f, acc3 = 0.f;
        const uint2* pHi = bfragHi + (size_t)og * 64 * 4 * 32 + lane;
        const uint2* pLo = bfragLo + (size_t)og * 64 * 4 * 32 + lane;
        const int bcol = og * 8 + t4 * 2;

#pragma unroll 2
        for (int i = 0; i < 64; i++) {
            uint2 bh[4], bl[4];
#pragma unroll
            for (int kt = 0; kt < 4; kt++) {
                bh[kt] = pHi[(i * 4 + kt) * 32];
                bl[kt] = pLo[(i * 4 + kt) * 32];
            }
            float dh[4] = {0.f, 0.f, 0.f, 0.f};   // hi*hi chain
            float dx[4] = {0.f, 0.f, 0.f, 0.f};   // cross-term chain
#pragma unroll
            for (int kt = 0; kt < 4; kt++) {
                mma_acc(dh, aHi[kt], bh[kt].x, bh[kt].y);
                mma_acc(dx, aHi[kt], bl[kt].x, bl[kt].y);
                mma_acc(dx, aLo[kt], bh[kt].x, bh[kt].y);
            }
            float hv0 = h_s[i * 128 + row0];
            float hv1 = h_s[i * 128 + row1];
            float bb0 = b2_s[i * 128 + bcol];
            float bb1 = b2_s[i * 128 + bcol + 1];
            float v0 = leaky(dh[0] + dx[0] + bb0);
            float v1 = leaky(dh[1] + dx[1] + bb1);
            float v2 = leaky(dh[2] + dx[2] + bb0);
            float v3 = leaky(dh[3] + dx[3] + bb1);
            acc0 += hv0 * v0;
            acc1 += hv0 * v1;
            acc2 += hv1 * v2;
            acc3 += hv1 * v3;
        }
        atomicAdd(&agg[d0 * 128 + bcol    ], acc0);
        atomicAdd(&agg[d0 * 128 + bcol + 1], acc1);
        atomicAdd(&agg[d1 * 128 + bcol    ], acc2);
        atomicAdd(&agg[d1 * 128 + bcol + 1], acc3);
    }
}

// ---------------- fused NNConv edge kernel (fp32, layers 1-2) ---------------
template <int IN, int OUT, int TILE_E>
__global__ __launch_bounds__(256)
void edge_conv_kernel(const float* __restrict__ x,
                      const float* __restrict__ h,
                      const int*   __restrict__ ei,
                      const float* __restrict__ w1,
                      const float* __restrict__ b1,
                      const float* __restrict__ w2,
                      const float* __restrict__ b2,
                      float*       __restrict__ agg)
{
    constexpr int CT  = OUT / 4;
    constexpr int ET  = 256 / CT;
    constexpr int EPT = TILE_E / ET;

    extern __shared__ float fsmem[];
    float* e_s    = fsmem;
    float* h_s    = e_s + TILE_E * 68;
    float* w2_s   = h_s + TILE_E * IN;
    float* b2_s   = w2_s + 64 * OUT;
    float* attr_s = b2_s + OUT;
    int*   src_s  = (int*)(attr_s + TILE_E * 3);
    int*   dst_s  = src_s + TILE_E;

    const int tid = threadIdx.x;
    const int e0  = blockIdx.x * TILE_E;

    for (int j = tid; j < TILE_E; j += 256) {
        int s = ei[e0 + j];
        int d = ei[N_EDGES + e0 + j];
        src_s[j] = s; dst_s[j] = d;
        attr_s[j * 3 + 0] = x[d * 4 + 1] - x[s * 4 + 1];
        attr_s[j * 3 + 1] = x[d * 4 + 2] - x[s * 4 + 2];
        attr_s[j * 3 + 2] = x[d * 4 + 3] - x[s * 4 + 3];
    }
    __syncthreads();

    for (int idx = tid; idx < TILE_E * (IN / 4); idx += 256) {
        int j = idx / (IN / 4), q = idx % (IN / 4);
        ((float4*)&h_s[j * IN])[q] = ((const float4*)&h[src_s[j] * IN])[q];
    }
    for (int idx = tid; idx < TILE_E * 64; idx += 256) {
        int j = idx >> 6, k = idx & 63;
        float a0 = attr_s[j * 3], a1 = attr_s[j * 3 + 1], a2 = attr_s[j * 3 + 2];
        e_s[j * 68 + k] = leaky(b1[k] + a0 * w1[k] + a1 * w1[64 + k] + a2 * w1[128 + k]);
    }

    const int ce = tid % CT;
    const int te = tid / CT;
    const int c0 = ce * 4;

    float acc[EPT][4];
#pragma unroll
    for (int j = 0; j < EPT; j++) { acc[j][0] = acc[j][1] = acc[j][2] = acc[j][3] = 0.f; }

    for (int i = 0; i < IN; i++) {
        __syncthreads();
        for (int idx = tid * 4; idx < 64 * OUT; idx += 1024) {
            int k = idx / OUT, o = idx % OUT;
            *(float4*)&w2_s[idx] = *(const float4*)&w2[k * (IN * OUT) + i * OUT + o];
        }
        if (tid < OUT) b2_s[tid] = b2[i * OUT + tid];
        __syncthreads();

        float c[EPT][4];
#pragma unroll
        for (int j = 0; j < EPT; j++) {
            c[j][0] = b2_s[c0];     c[j][1] = b2_s[c0 + 1];
            c[j][2] = b2_s[c0 + 2]; c[j][3] = b2_s[c0 + 3];
        }
        for (int k = 0; k < 64; k += 4) {
            float4 w0 = *(const float4*)&w2_s[(k + 0) * OUT + c0];
            float4 wA = *(const float4*)&w2_s[(k + 1) * OUT + c0];
            float4 wB = *(const float4*)&w2_s[(k + 2) * OUT + c0];
            float4 wC = *(const float4*)&w2_s[(k + 3) * OUT + c0];
#pragma unroll
            for (int j = 0; j < EPT; j++) {
                int eg = te + j * ET;
                float4 ev = *(const float4*)&e_s[eg * 68 + k];
                c[j][0] += ev.x * w0.x + ev.y * wA.x + ev.z * wB.x + ev.w * wC.x;
                c[j][1] += ev.x * w0.y + ev.y * wA.y + ev.z * wB.y + ev.w * wC.y;
                c[j][2] += ev.x * w0.z + ev.y * wA.z + ev.z * wB.z + ev.w * wC.z;
                c[j][3] += ev.x * w0.w + ev.y * wA.w + ev.z * wB.w + ev.w * wC.w;
            }
        }
#pragma unroll
        for (int j = 0; j < EPT; j++) {
            int eg = te + j * ET;
            float hv = h_s[eg * IN + i];
            acc[j][0] += hv * leaky(c[j][0]);
            acc[j][1] += hv * leaky(c[j][1]);
            acc[j][2] += hv * leaky(c[j][2]);
            acc[j][3] += hv * leaky(c[j][3]);
        }
    }

#pragma unroll
    for (int j = 0; j < EPT; j++) {
        int eg = te + j * ET;
        int d  = dst_s[eg];
        atomicAdd(&agg[d * OUT + c0 + 0], acc[j][0]);
        atomicAdd(&agg[d * OUT + c0 + 1], acc[j][1]);
        atomicAdd(&agg[d * OUT + c0 + 2], acc[j][2]);
        atomicAdd(&agg[d * OUT + c0 + 3], acc[j][3]);
    }
}

// ---------------- node update: h_next = leaky(agg + h @ root + cb) ---------
__global__ void node_update_kernel(const float* __restrict__ h,
                                   const float* __restrict__ agg,
                                   const float* __restrict__ root,
                                   const float* __restrict__ cb,
                                   float* __restrict__ out,
                                   int IN, int OUT)
{
    int gid = blockIdx.x * blockDim.x + threadIdx.x;
    if (gid >= N_NODES * OUT) return;
    int n = gid / OUT, o = gid % OUT;
    float t = agg[gid] + cb[o];
    for (int i = 0; i < IN; i++) t += h[n * IN + i] * root[i * OUT + o];
    out[gid] = leaky(t);
}

// ---------------- sum-pool over sorted batch_index --------------------------
#define POOL_CHUNK 50
__global__ void pool_kernel(const float* __restrict__ h3,
                            const int*   __restrict__ batch,
                            float*       __restrict__ g)
{
    int o  = threadIdx.x;
    int n0 = blockIdx.x * POOL_CHUNK;
    int n1 = n0 + POOL_CHUNK; if (n1 > N_NODES) n1 = N_NODES;
    float s = 0.f;
    int cur = batch[n0];
    for (int n = n0; n < n1; n++) {
        int b = batch[n];
        if (b != cur) { atomicAdd(&g[cur * 128 + o], s); s = 0.f; cur = b; }
        s += h3[n * 128 + o];
    }
    atomicAdd(&g[cur * 128 + o], s);
}

// ---------------- readout MLP: 128->128->64->1 ------------------------------
__global__ void readout_kernel(const float* __restrict__ g,
                               const float* __restrict__ w1, const float* __restrict__ b1,
                               const float* __restrict__ w2, const float* __restrict__ b2,
                               const float* __restrict__ w3, const float* __restrict__ b3,
                               float* __restrict__ out)
{
    __shared__ float gin[128], g1[128], g2[64];
    int b = blockIdx.x, t = threadIdx.x;
    gin[t] = g[b * 128 + t];
    __syncthreads();
    float s = b1[t];
    for (int i = 0; i < 128; i++) s += gin[i] * w1[i * 128 + t];
    g1[t] = leaky(s);
    __syncthreads();
    if (t < 64) {
        float s2 = b2[t];
        for (int i = 0; i < 128; i++) s2 += g1[i] * w2[i * 64 + t];
        g2[t] = leaky(s2);
    }
    __syncthreads();
    if (t < 64) g1[t] = g2[t] * w3[t];
    __syncthreads();
    if (t == 0) {
        float s3 = b3[0];
        for (int i = 0; i < 64; i++) s3 += g1[i];
        out[b] = s3;
    }
}

// ---------------- launch ----------------------------------------------------
static constexpr int smem_bytes(int IN, int OUT, int TE) {
    return 4 * (TE * 68 + TE * IN + 64 * OUT + OUT + TE * 3) + 8 * TE;
}

extern "C" void kernel_launch(void* const* d_in, const int* in_sizes, int n_in,
                              void* d_out, int out_size)
{
    const float* x       = (const float*)d_in[0];
    const int*   ei      = (const int*)  d_in[1];
    const int*   batch   = (const int*)  d_in[2];
    const float* en1_w1  = (const float*)d_in[3];
    const float* en1_b1  = (const float*)d_in[4];
    const float* en1_w2  = (const float*)d_in[5];
    const float* en1_b2  = (const float*)d_in[6];
    const float* en2_w1  = (const float*)d_in[7];
    const float* en2_b1  = (const float*)d_in[8];
    const float* en2_w2  = (const float*)d_in[9];
    const float* en2_b2  = (const float*)d_in[10];
    const float* en3_w1  = (const float*)d_in[11];
    const float* en3_b1  = (const float*)d_in[12];
    const float* en3_w2  = (const float*)d_in[13];
    const float* en3_b2  = (const float*)d_in[14];
    const float* root1   = (const float*)d_in[15];
    const float* cb1     = (const float*)d_in[16];
    const float* root2   = (const float*)d_in[17];
    const float* cb2     = (const float*)d_in[18];
    const float* root3   = (const float*)d_in[19];
    const float* cb3     = (const float*)d_in[20];
    const float* fc1_w   = (const float*)d_in[21];
    const float* fc1_b   = (const float*)d_in[22];
    const float* fc2_w   = (const float*)d_in[23];
    const float* fc2_b   = (const float*)d_in[24];
    const float* fc3_w   = (const float*)d_in[25];
    const float* fc3_b   = (const float*)d_in[26];

    float *h1, *h2, *h3, *agg, *gp;
    uint2 *fhi, *flo;
    cudaGetSymbolAddress((void**)&h1,  g_h1);
    cudaGetSymbolAddress((void**)&h2,  g_h2);
    cudaGetSymbolAddress((void**)&h3,  g_h3);
    cudaGetSymbolAddress((void**)&agg, g_agg);
    cudaGetSymbolAddress((void**)&gp,  g_pool);
    cudaGetSymbolAddress((void**)&fhi, g_bfrag_hi);
    cudaGetSymbolAddress((void**)&flo, g_bfrag_lo);

    constexpr int S1 = smem_bytes(4, 8, 128);
    constexpr int S2 = smem_bytes(8, 64, 64);
    cudaFuncSetAttribute(edge_conv3_mma,
                         cudaFuncAttributeMaxDynamicSharedMemorySize, SMEM3_BYTES);

    // ---- prep: rearrange layer-3 w2 into bf16 hi/lo mma fragments
    prep_w2_frag<<<(16 * 64 * 4 * 32 + 255) / 256, 256>>>(en3_w2, fhi, flo);

    // ---- layer 1: in=4, out=8
    zero_kernel<<<(N_NODES * 8 + 255) / 256, 256>>>(agg, N_NODES * 8);
    edge_conv_kernel<4, 8, 128><<<N_EDGES / 128, 256, S1>>>(
        x, x, ei, en1_w1, en1_b1, en1_w2, en1_b2, agg);
    node_update_kernel<<<(N_NODES * 8 + 255) / 256, 256>>>(x, agg, root1, cb1, h1, 4, 8);

    // ---- layer 2: in=8, out=64
    zero_kernel<<<(N_NODES * 64 + 255) / 256, 256>>>(agg, N_NODES * 64);
    edge_conv_kernel<8, 64, 64><<<N_EDGES / 64, 256, S2>>>(
        x, h1, ei, en2_w1, en2_b1, en2_w2, en2_b2, agg);
    node_update_kernel<<<(N_NODES * 64 + 255) / 256, 256>>>(h1, agg, root2, cb2, h2, 8, 64);

    // ---- layer 3: in=64, out=128 — mma.sync bf16 compensated
    zero_kernel<<<(N_NODES * 128 + 255) / 256, 256>>>(agg, N_NODES * 128);
    edge_conv3_mma<<<N_EDGES / 128, 256, SMEM3_BYTES>>>(
        x, h2, ei, en3_w1, en3_b1, fhi, flo, en3_b2, agg);
    node_update_kernel<<<(N_NODES * 128 + 255) / 256, 256>>>(h2, agg, root3, cb3, h3, 64, 128);

    // ---- pool + readout
    zero_kernel<<<(N_GRAPHS * 128 + 255) / 256, 256>>>(gp, N_GRAPHS * 128);
    pool_kernel<<<(N_NODES + POOL_CHUNK - 1) / POOL_CHUNK, 128>>>(h3, batch, gp);
    readout_kernel<<<N_GRAPHS, 128>>>(gp, fc1_w, fc1_b, fc2_w, fc2_b, fc3_w, fc3_b,
                                      (float*)d_out);
}